// round 1
// baseline (speedup 1.0000x reference)
#include <cuda_runtime.h>
#include <math_constants.h>

#define N_ROWS   16384
#define N_CODES  8192
#define DIM      256

#define BM 64      // rows of x per block
#define BN 128     // codes per tile
#define BK 16      // dim chunk per stage
#define XS_LD 68   // padded row stride (over BM) for transposed x tile

__device__ float g_xx[N_ROWS];
__device__ float g_ww[N_CODES];
__device__ int   g_idx[N_ROWS];

// ---------------------------------------------------------------------------
// Kernel 1: per-row sum of squares for x (16384 rows) and weight (8192 rows).
// Sequential ascending order, rounded mul then add (mimic a+b chain, no FMA).
// ---------------------------------------------------------------------------
__global__ void sumsq_kernel(const float* __restrict__ x,
                             const float* __restrict__ w) {
    int t = blockIdx.x * blockDim.x + threadIdx.x;
    if (t < N_ROWS) {
        const float4* p = (const float4*)(x + (size_t)t * DIM);
        float acc = 0.0f;
#pragma unroll 8
        for (int j = 0; j < DIM / 4; j++) {
            float4 v = p[j];
            acc = __fadd_rn(acc, __fmul_rn(v.x, v.x));
            acc = __fadd_rn(acc, __fmul_rn(v.y, v.y));
            acc = __fadd_rn(acc, __fmul_rn(v.z, v.z));
            acc = __fadd_rn(acc, __fmul_rn(v.w, v.w));
        }
        g_xx[t] = acc;
    } else if (t < N_ROWS + N_CODES) {
        int r = t - N_ROWS;
        const float4* p = (const float4*)(w + (size_t)r * DIM);
        float acc = 0.0f;
#pragma unroll 8
        for (int j = 0; j < DIM / 4; j++) {
            float4 v = p[j];
            acc = __fadd_rn(acc, __fmul_rn(v.x, v.x));
            acc = __fadd_rn(acc, __fmul_rn(v.y, v.y));
            acc = __fadd_rn(acc, __fmul_rn(v.z, v.z));
            acc = __fadd_rn(acc, __fmul_rn(v.w, v.w));
        }
        g_ww[r] = acc;
    }
}

// ---------------------------------------------------------------------------
// Kernel 2: fused GEMM + argmin.
// Block: 256 threads (16x16), BM=64 rows, loops all 8192 codes in BN=128 tiles.
// x tile [DIM][BM] transposed in smem (69.6 KB), W tile [BK][BN] staged (8 KB).
// Each thread: 4 rows x 8 codes register tile, running (min,idx) per row.
// Distance replicates reference rounding: d = fl( fl(xx+ww) + fl(-2*s) ).
// ---------------------------------------------------------------------------
__global__ void __launch_bounds__(256)
vq_argmin_kernel(const float* __restrict__ x, const float* __restrict__ w) {
    extern __shared__ float smem[];
    float* Xs = smem;                      // [DIM][XS_LD] -> DIM*XS_LD floats
    float* Bs = smem + DIM * XS_LD;        // [BK][BN]

    const int tid = threadIdx.x;
    const int tx = tid & 15;               // code group 0..15 (8 codes each)
    const int ty = tid >> 4;               // row group 0..15 (4 rows each)
    const int rowBase = blockIdx.x * BM;

    // --- load + transpose x tile: Xs[d][r] = x[rowBase+r][d] ---
    {
        int r = tid >> 2;                  // 0..63
        int q = tid & 3;                   // 0..3, covers d chunk q*64..q*64+63
        const float4* src = (const float4*)(x + (size_t)(rowBase + r) * DIM + q * 64);
#pragma unroll
        for (int j = 0; j < 16; j++) {
            float4 v = src[j];
            int d = q * 64 + j * 4;
            Xs[(d + 0) * XS_LD + r] = v.x;
            Xs[(d + 1) * XS_LD + r] = v.y;
            Xs[(d + 2) * XS_LD + r] = v.z;
            Xs[(d + 3) * XS_LD + r] = v.w;
        }
    }

    float xxf[4];
#pragma unroll
    for (int i = 0; i < 4; i++) xxf[i] = g_xx[rowBase + ty * 4 + i];

    float bestv[4];
    int   besti[4];
#pragma unroll
    for (int i = 0; i < 4; i++) { bestv[i] = CUDART_INF_F; besti[i] = 0x7fffffff; }

    __syncthreads();

    for (int ct = 0; ct < N_CODES / BN; ct++) {
        float acc[4][8];
#pragma unroll
        for (int i = 0; i < 4; i++)
#pragma unroll
            for (int j = 0; j < 8; j++) acc[i][j] = 0.0f;

        float wwf[8];
#pragma unroll
        for (int j = 0; j < 8; j++) wwf[j] = g_ww[ct * BN + tx * 8 + j];

        for (int ks = 0; ks < DIM / BK; ks++) {
            __syncthreads();               // protect Bs from previous stage readers
            {   // stage W tile: Bs[dd][c] = w[ct*BN + c][ks*BK + dd]
                int c = tid >> 1;          // 0..127
                int q = tid & 1;           // 0..1
                const float4* src = (const float4*)(w + (size_t)(ct * BN + c) * DIM + ks * BK);
#pragma unroll
                for (int j = 0; j < 2; j++) {
                    float4 v = src[q * 2 + j];
                    int dd = (q * 2 + j) * 4;
                    Bs[(dd + 0) * BN + c] = v.x;
                    Bs[(dd + 1) * BN + c] = v.y;
                    Bs[(dd + 2) * BN + c] = v.z;
                    Bs[(dd + 3) * BN + c] = v.w;
                }
            }
            __syncthreads();

#pragma unroll
            for (int kk = 0; kk < BK; kk++) {
                int d = ks * BK + kk;
                float4 a  = *(const float4*)&Xs[d * XS_LD + ty * 4];
                float4 b0 = *(const float4*)&Bs[kk * BN + tx * 8];
                float4 b1 = *(const float4*)&Bs[kk * BN + tx * 8 + 4];
                float av[4] = {a.x, a.y, a.z, a.w};
                float bv[8] = {b0.x, b0.y, b0.z, b0.w, b1.x, b1.y, b1.z, b1.w};
#pragma unroll
                for (int i = 0; i < 4; i++)
#pragma unroll
                    for (int j = 0; j < 8; j++)
                        acc[i][j] = __fmaf_rn(av[i], bv[j], acc[i][j]);
            }
        }

        // epilogue: distances + running argmin (ascending code order => first-index ties)
#pragma unroll
        for (int i = 0; i < 4; i++) {
#pragma unroll
            for (int j = 0; j < 8; j++) {
                float t = __fadd_rn(xxf[i], wwf[j]);
                float dq = __fadd_rn(t, __fmul_rn(-2.0f, acc[i][j]));
                int code = ct * BN + tx * 8 + j;
                if (dq < bestv[i]) { bestv[i] = dq; besti[i] = code; }
            }
        }
    }

    // cross-thread reduction: 16 candidates per row, lexicographic (val, idx) min
    __syncthreads();
    float* rv = smem;                       // 64*16 floats
    int*   ri = (int*)(smem + BM * 16);     // 64*16 ints
#pragma unroll
    for (int i = 0; i < 4; i++) {
        rv[(ty * 4 + i) * 16 + tx] = bestv[i];
        ri[(ty * 4 + i) * 16 + tx] = besti[i];
    }
    __syncthreads();
    if (tid < BM) {
        float bv = CUDART_INF_F;
        int   bi = 0x7fffffff;
#pragma unroll
        for (int t = 0; t < 16; t++) {
            float v = rv[tid * 16 + t];
            int   id = ri[tid * 16 + t];
            if (v < bv || (v == bv && id < bi)) { bv = v; bi = id; }
        }
        g_idx[rowBase + tid] = bi;
    }
}

// ---------------------------------------------------------------------------
// Kernel 3: gather quantized rows + optional index tail (as float).
// ---------------------------------------------------------------------------
__global__ void gather_kernel(const float* __restrict__ w, float* __restrict__ out,
                              int out_size) {
    int i = blockIdx.x * blockDim.x + threadIdx.x;   // over N_ROWS*64 float4
    if (i < N_ROWS * (DIM / 4)) {
        int row = i >> 6;
        int c   = i & 63;
        int k = g_idx[row];
        float4 v = ((const float4*)(w + (size_t)k * DIM))[c];
        ((float4*)out)[i] = v;
    }
    if (i < N_ROWS && out_size >= N_ROWS * DIM + N_ROWS) {
        out[N_ROWS * DIM + i] = (float)g_idx[i];
    }
}

// ---------------------------------------------------------------------------
extern "C" void kernel_launch(void* const* d_in, const int* in_sizes, int n_in,
                              void* d_out, int out_size) {
    const float* x = (const float*)d_in[0];
    const float* w = (const float*)d_in[1];
    float* out = (float*)d_out;

    static bool attr_set = false;
    size_t smem_bytes = (size_t)(DIM * XS_LD + BK * BN) * sizeof(float); // ~77.8 KB
    if (!attr_set) {
        cudaFuncSetAttribute(vq_argmin_kernel,
                             cudaFuncAttributeMaxDynamicSharedMemorySize,
                             (int)smem_bytes);
        attr_set = true;
    }

    {   // sum of squares for x rows and w rows
        int total = N_ROWS + N_CODES;
        sumsq_kernel<<<(total + 255) / 256, 256>>>(x, w);
    }
    {   // fused GEMM + argmin
        vq_argmin_kernel<<<N_ROWS / BM, 256, smem_bytes>>>(x, w);
    }
    {   // gather
        int total4 = N_ROWS * (DIM / 4);
        gather_kernel<<<(total4 + 255) / 256, 256>>>(w, out, out_size);
    }
}

// round 3
// speedup vs baseline: 2.7085x; 2.7085x over previous
#include <cuda_runtime.h>
#include <cuda_bf16.h>
#include <cuda_fp16.h>
#include <math_constants.h>
#include <cstdint>

#define N_ROWS   16384
#define N_CODES  8192
#define DIM      256

// GEMM tiling
#define TM 128           // rows per CTA
#define TN 256           // codes per CTA
#define LDA32 132        // 32-bit words per padded smem row (264 bf16 = 528B)
#define LDAB  528        // bytes per padded smem row

#define AS_BYTES (128 * LDAB)            // 67584
#define BS_BYTES (256 * LDAB)            // 135168
#define G_SMEM   (AS_BYTES + BS_BYTES + 256 * 4)   // + ws[256]

// ---------------------------------------------------------------------------
// device scratch (static: no allocations allowed)
// ---------------------------------------------------------------------------
__device__ float         g_xx[N_ROWS];              // exact ||x||^2 (ref rounding)
__device__ float         g_ax[N_ROWS];              // sum |x_i| (error bound)
__device__ float         g_ww[N_CODES];             // exact ||w||^2
__device__ unsigned int  g_rowmin[N_ROWS];          // encoded approx min dist
__device__ int           g_idx[N_ROWS];             // final argmin
__device__ unsigned int  g_wmax;                    // bits of max |w| (>=0)
__device__ __nv_bfloat16 g_xbf[N_ROWS * DIM];       // bf16 copy of x
__device__ __nv_bfloat16 g_wbf[N_CODES * DIM];      // bf16 copy of w
__device__ __half        g_dist[(size_t)N_ROWS * N_CODES];  // approx distances

// monotone float<->uint encoding for atomicMin on possibly-negative floats
__device__ __forceinline__ unsigned int enc_f(float f) {
    unsigned int u = __float_as_uint(f);
    return (u & 0x80000000u) ? ~u : (u | 0x80000000u);
}
__device__ __forceinline__ float dec_f(unsigned int u) {
    return (u & 0x80000000u) ? __uint_as_float(u ^ 0x80000000u)
                             : __uint_as_float(~u);
}

// m16n8k16 bf16 HMMA (valid in compute_103 PTX: no tcgen05 features)
__device__ __forceinline__ void mma16816(float* c, const uint32_t* a,
                                         const uint32_t* b) {
    asm volatile(
        "mma.sync.aligned.m16n8k16.row.col.f32.bf16.bf16.f32 "
        "{%0,%1,%2,%3}, {%4,%5,%6,%7}, {%8,%9}, {%0,%1,%2,%3};"
        : "+f"(c[0]), "+f"(c[1]), "+f"(c[2]), "+f"(c[3])
        : "r"(a[0]), "r"(a[1]), "r"(a[2]), "r"(a[3]), "r"(b[0]), "r"(b[1]));
}

// ---------------------------------------------------------------------------
// Kernel P: exact row stats (R1-validated rounding chain), bf16 casts,
// wmax, rowmin init.
// ---------------------------------------------------------------------------
__global__ void prep_kernel(const float* __restrict__ x,
                            const float* __restrict__ w) {
    int t = blockIdx.x * blockDim.x + threadIdx.x;
    if (t < N_ROWS) {
        const float4* p = (const float4*)(x + (size_t)t * DIM);
        uint4* dst = (uint4*)(g_xbf + (size_t)t * DIM);
        float acc = 0.0f, aacc = 0.0f;
#pragma unroll 4
        for (int j = 0; j < 32; j++) {
            float4 v0 = p[2 * j], v1 = p[2 * j + 1];
            acc = __fadd_rn(acc, __fmul_rn(v0.x, v0.x));
            acc = __fadd_rn(acc, __fmul_rn(v0.y, v0.y));
            acc = __fadd_rn(acc, __fmul_rn(v0.z, v0.z));
            acc = __fadd_rn(acc, __fmul_rn(v0.w, v0.w));
            acc = __fadd_rn(acc, __fmul_rn(v1.x, v1.x));
            acc = __fadd_rn(acc, __fmul_rn(v1.y, v1.y));
            acc = __fadd_rn(acc, __fmul_rn(v1.z, v1.z));
            acc = __fadd_rn(acc, __fmul_rn(v1.w, v1.w));
            aacc += fabsf(v0.x) + fabsf(v0.y) + fabsf(v0.z) + fabsf(v0.w)
                  + fabsf(v1.x) + fabsf(v1.y) + fabsf(v1.z) + fabsf(v1.w);
            __nv_bfloat162 b0, b1, b2, b3;
            b0.x = __float2bfloat16_rn(v0.x); b0.y = __float2bfloat16_rn(v0.y);
            b1.x = __float2bfloat16_rn(v0.z); b1.y = __float2bfloat16_rn(v0.w);
            b2.x = __float2bfloat16_rn(v1.x); b2.y = __float2bfloat16_rn(v1.y);
            b3.x = __float2bfloat16_rn(v1.z); b3.y = __float2bfloat16_rn(v1.w);
            uint4 o;
            o.x = *(unsigned int*)&b0; o.y = *(unsigned int*)&b1;
            o.z = *(unsigned int*)&b2; o.w = *(unsigned int*)&b3;
            dst[j] = o;
        }
        g_xx[t] = acc;
        g_ax[t] = aacc;
        g_rowmin[t] = 0xFFFFFFFFu;
    } else if (t < N_ROWS + N_CODES) {
        int r = t - N_ROWS;
        const float4* p = (const float4*)(w + (size_t)r * DIM);
        uint4* dst = (uint4*)(g_wbf + (size_t)r * DIM);
        float acc = 0.0f, amax = 0.0f;
#pragma unroll 4
        for (int j = 0; j < 32; j++) {
            float4 v0 = p[2 * j], v1 = p[2 * j + 1];
            acc = __fadd_rn(acc, __fmul_rn(v0.x, v0.x));
            acc = __fadd_rn(acc, __fmul_rn(v0.y, v0.y));
            acc = __fadd_rn(acc, __fmul_rn(v0.z, v0.z));
            acc = __fadd_rn(acc, __fmul_rn(v0.w, v0.w));
            acc = __fadd_rn(acc, __fmul_rn(v1.x, v1.x));
            acc = __fadd_rn(acc, __fmul_rn(v1.y, v1.y));
            acc = __fadd_rn(acc, __fmul_rn(v1.z, v1.z));
            acc = __fadd_rn(acc, __fmul_rn(v1.w, v1.w));
            amax = fmaxf(amax, fmaxf(fmaxf(fabsf(v0.x), fabsf(v0.y)),
                                     fmaxf(fabsf(v0.z), fabsf(v0.w))));
            amax = fmaxf(amax, fmaxf(fmaxf(fabsf(v1.x), fabsf(v1.y)),
                                     fmaxf(fabsf(v1.z), fabsf(v1.w))));
            __nv_bfloat162 b0, b1, b2, b3;
            b0.x = __float2bfloat16_rn(v0.x); b0.y = __float2bfloat16_rn(v0.y);
            b1.x = __float2bfloat16_rn(v0.z); b1.y = __float2bfloat16_rn(v0.w);
            b2.x = __float2bfloat16_rn(v1.x); b2.y = __float2bfloat16_rn(v1.y);
            b3.x = __float2bfloat16_rn(v1.z); b3.y = __float2bfloat16_rn(v1.w);
            uint4 o;
            o.x = *(unsigned int*)&b0; o.y = *(unsigned int*)&b1;
            o.z = *(unsigned int*)&b2; o.w = *(unsigned int*)&b3;
            dst[j] = o;
        }
        g_ww[r] = acc;
        atomicMax(&g_wmax, __float_as_uint(amax));  // amax >= 0: uint order ok
    }
}

// ---------------------------------------------------------------------------
// Kernel G: bf16 HMMA GEMM 128x256x256 per CTA. Whole K resident in smem.
// 8 warps (wm 0..1, wn 0..3), warp tile 64x64, frag grid 4(m16) x 8(n8).
// Epilogue: d = ww - 2s -> half -> g_dist; per-row min -> atomicMin g_rowmin.
// ---------------------------------------------------------------------------
__global__ void __launch_bounds__(256)
vq_gemm_kernel() {
    extern __shared__ char sm[];
    char*  As   = sm;                          // [128][528B]
    char*  Bs   = sm + AS_BYTES;               // [256][528B]
    float* ws   = (float*)(sm + AS_BYTES + BS_BYTES);
    const uint32_t* As32 = (const uint32_t*)As;
    const uint32_t* Bs32 = (const uint32_t*)Bs;

    const int tid  = threadIdx.x;
    const int wid  = tid >> 5;
    const int lane = tid & 31;
    const int wm   = wid & 1;     // 0..1 (64 rows each)
    const int wn   = wid >> 1;    // 0..3 (64 cols each)
    const int g    = lane >> 2;   // 0..7
    const int tg   = lane & 3;    // 0..3
    const int codeBase = blockIdx.x * TN;
    const int rowBase  = blockIdx.y * TM;

    // stage A tile: 128 rows x 512B -> padded rows of 528B
#pragma unroll
    for (int i = 0; i < 16; i++) {
        int c = tid + i * 256;                 // 0..4095 16B-chunks
        int r = c >> 5;
        int k16 = c & 31;
        uint4 v = *(const uint4*)(g_xbf + (size_t)(rowBase + r) * DIM + k16 * 8);
        *(uint4*)(As + r * LDAB + k16 * 16) = v;
    }
    // stage B tile: 256 rows x 512B
#pragma unroll
    for (int i = 0; i < 32; i++) {
        int c = tid + i * 256;                 // 0..8191
        int r = c >> 5;
        int k16 = c & 31;
        uint4 v = *(const uint4*)(g_wbf + (size_t)(codeBase + r) * DIM + k16 * 8);
        *(uint4*)(Bs + r * LDAB + k16 * 16) = v;
    }
    ws[tid] = g_ww[codeBase + tid];
    __syncthreads();

    float acc[4][8][4];
#pragma unroll
    for (int mi = 0; mi < 4; mi++)
#pragma unroll
        for (int ni = 0; ni < 8; ni++)
#pragma unroll
            for (int e = 0; e < 4; e++) acc[mi][ni][e] = 0.0f;

#pragma unroll
    for (int ks = 0; ks < 16; ks++) {
        uint32_t a[4][4];
#pragma unroll
        for (int mi = 0; mi < 4; mi++) {
            int r0 = wm * 64 + mi * 16 + g;
            int kw = ks * 8 + tg;
            a[mi][0] = As32[r0 * LDA32 + kw];
            a[mi][1] = As32[(r0 + 8) * LDA32 + kw];
            a[mi][2] = As32[r0 * LDA32 + kw + 4];
            a[mi][3] = As32[(r0 + 8) * LDA32 + kw + 4];
        }
        uint32_t b[8][2];
#pragma unroll
        for (int ni = 0; ni < 8; ni++) {
            int n = wn * 64 + ni * 8 + g;
            int kw = ks * 8 + tg;
            b[ni][0] = Bs32[n * LDA32 + kw];
            b[ni][1] = Bs32[n * LDA32 + kw + 4];
        }
#pragma unroll
        for (int mi = 0; mi < 4; mi++)
#pragma unroll
            for (int ni = 0; ni < 8; ni++)
                mma16816(acc[mi][ni], a[mi], b[ni]);
    }

    // epilogue: distances, half store, per-row min
#pragma unroll
    for (int mi = 0; mi < 4; mi++) {
        int row_lo = rowBase + wm * 64 + mi * 16 + g;
        int row_hi = row_lo + 8;
        float mlo = CUDART_INF_F, mhi = CUDART_INF_F;
#pragma unroll
        for (int ni = 0; ni < 8; ni++) {
            int cloc = wn * 64 + ni * 8 + tg * 2;
            float ww0 = ws[cloc], ww1 = ws[cloc + 1];
            float d0 = __fmaf_rn(-2.0f, acc[mi][ni][0], ww0);
            float d1 = __fmaf_rn(-2.0f, acc[mi][ni][1], ww1);
            float d2 = __fmaf_rn(-2.0f, acc[mi][ni][2], ww0);
            float d3 = __fmaf_rn(-2.0f, acc[mi][ni][3], ww1);
            __half h0 = __float2half_rn(d0), h1 = __float2half_rn(d1);
            __half h2 = __float2half_rn(d2), h3 = __float2half_rn(d3);
            *(__half2*)(g_dist + (size_t)row_lo * N_CODES + codeBase + cloc) =
                __halves2half2(h0, h1);
            *(__half2*)(g_dist + (size_t)row_hi * N_CODES + codeBase + cloc) =
                __halves2half2(h2, h3);
            mlo = fminf(mlo, fminf(__half2float(h0), __half2float(h1)));
            mhi = fminf(mhi, fminf(__half2float(h2), __half2float(h3)));
        }
        // reduce over the 4 lanes sharing this row (lane bits 0..1)
        mlo = fminf(mlo, __shfl_xor_sync(0xFFFFFFFF, mlo, 1));
        mlo = fminf(mlo, __shfl_xor_sync(0xFFFFFFFF, mlo, 2));
        mhi = fminf(mhi, __shfl_xor_sync(0xFFFFFFFF, mhi, 1));
        mhi = fminf(mhi, __shfl_xor_sync(0xFFFFFFFF, mhi, 2));
        if (tg == 0) {
            atomicMin(&g_rowmin[row_lo], enc_f(mlo));
            atomicMin(&g_rowmin[row_hi], enc_f(mhi));
        }
    }
}

// ---------------------------------------------------------------------------
// Kernel F: per-row scan of approx distances; exact fp32 rescore of candidates
// within margin; quantized compare with first-index tie-break. 1 warp / row.
// ---------------------------------------------------------------------------
__global__ void __launch_bounds__(256)
select_kernel(const float* __restrict__ x, const float* __restrict__ w) {
    const int row  = blockIdx.x * 8 + (threadIdx.x >> 5);
    const int lane = threadIdx.x & 31;

    const float wmaxv = __uint_as_float(g_wmax);
    const float xx = g_xx[row];
    const float ax = g_ax[row];
    const float mn = dec_f(g_rowmin[row]);
    // margin: 2x bf16-mma error + quantized-tie span + half rounding + safety
    const float margin = 0.033f * ax * wmaxv + xx * 1.9073486e-6f + 2e-4f;
    const float thr = mn + margin;

    const __half* dr = g_dist + (size_t)row * N_CODES;
    const float* xr = x + (size_t)row * DIM;

    float bv = CUDART_INF_F;
    int   bi = 0x7fffffff;

#pragma unroll 1
    for (int j = 0; j < 32; j++) {
        int cbase = (j * 32 + lane) * 8;
        uint4 v = *(const uint4*)(dr + cbase);
        const __half2* hp = (const __half2*)&v;
#pragma unroll
        for (int e = 0; e < 4; e++) {
            float2 f = __half22float2(hp[e]);
#pragma unroll
            for (int q = 0; q < 2; q++) {
                float dv = (q == 0) ? f.x : f.y;
                if (dv <= thr) {
                    int code = cbase + 2 * e + q;
                    const float* wr = w + (size_t)code * DIM;
                    float s = 0.0f;
#pragma unroll 8
                    for (int k = 0; k < DIM; k++)
                        s = __fmaf_rn(xr[k], wr[k], s);
                    float tq = __fadd_rn(xx, g_ww[code]);
                    float dq = __fadd_rn(tq, __fmul_rn(-2.0f, s));
                    if (dq < bv || (dq == bv && code < bi)) { bv = dq; bi = code; }
                }
            }
        }
    }
    // warp lexicographic (val, idx) reduction
#pragma unroll
    for (int off = 16; off > 0; off >>= 1) {
        float ov = __shfl_xor_sync(0xFFFFFFFF, bv, off);
        int   oi = __shfl_xor_sync(0xFFFFFFFF, bi, off);
        if (ov < bv || (ov == bv && oi < bi)) { bv = ov; bi = oi; }
    }
    if (lane == 0) g_idx[row] = bi;
}

// ---------------------------------------------------------------------------
// Kernel 4: gather quantized rows + index tail (as float) if present.
// ---------------------------------------------------------------------------
__global__ void gather_kernel(const float* __restrict__ w, float* __restrict__ out,
                              int out_size) {
    int i = blockIdx.x * blockDim.x + threadIdx.x;
    if (i < N_ROWS * (DIM / 4)) {
        int row = i >> 6;
        int c = i & 63;
        int k = g_idx[row];
        float4 v = ((const float4*)(w + (size_t)k * DIM))[c];
        ((float4*)out)[i] = v;
    }
    if (i < N_ROWS && out_size >= N_ROWS * DIM + N_ROWS) {
        out[N_ROWS * DIM + i] = (float)g_idx[i];
    }
}

// ---------------------------------------------------------------------------
extern "C" void kernel_launch(void* const* d_in, const int* in_sizes, int n_in,
                              void* d_out, int out_size) {
    const float* x = (const float*)d_in[0];
    const float* w = (const float*)d_in[1];
    float* out = (float*)d_out;

    static bool attr_set = false;
    if (!attr_set) {
        cudaFuncSetAttribute(vq_gemm_kernel,
                             cudaFuncAttributeMaxDynamicSharedMemorySize, G_SMEM);
        attr_set = true;
    }

    {   // P: stats + bf16 casts
        int total = N_ROWS + N_CODES;
        prep_kernel<<<(total + 255) / 256, 256>>>(x, w);
    }
    {   // G: tensor-core approximate distance GEMM (HMMA)
        dim3 grid(N_CODES / TN, N_ROWS / TM);   // (32, 128)
        vq_gemm_kernel<<<grid, 256, G_SMEM>>>();
    }
    {   // F: candidate filter + exact rescore
        select_kernel<<<N_ROWS / 8, 256>>>(x, w);
    }
    {   // gather
        int total4 = N_ROWS * (DIM / 4);
        gather_kernel<<<(total4 + 255) / 256, 256>>>(w, out, out_size);
    }
}

// round 4
// speedup vs baseline: 5.0967x; 1.8818x over previous
#include <cuda_runtime.h>
#include <cuda_bf16.h>
#include <cuda_fp16.h>
#include <math_constants.h>
#include <cstdint>

#define N_ROWS   16384
#define N_CODES  8192
#define DIM      256

#define TM 128
#define TN 256
#define LDA32 132        // padded row: 132 words = 528 B
#define LDAB  528
#define CAP   1024       // candidate slots per row

#define AS_BYTES (128 * LDAB)
#define BS_BYTES (256 * LDAB)
#define G_SMEM   (AS_BYTES + BS_BYTES + 256 * 4 + 128 * 4)

// ---------------------------------------------------------------------------
__device__ float         g_xx[N_ROWS];
__device__ float         g_ax[N_ROWS];
__device__ float         g_ww[N_CODES];
__device__ unsigned int  g_rowmin[N_ROWS];          // encoded approx min
__device__ unsigned int  g_cnt[N_ROWS];             // candidate counts
__device__ uint2         g_cand[(size_t)N_ROWS * CAP];  // {enc_dist, code}
__device__ int           g_idx[N_ROWS];
__device__ unsigned int  g_wmax;
__device__ __nv_bfloat16 g_xbf[N_ROWS * DIM];
__device__ __nv_bfloat16 g_wbf[N_CODES * DIM];

__device__ __forceinline__ unsigned int enc_f(float f) {
    unsigned int u = __float_as_uint(f);
    return (u & 0x80000000u) ? ~u : (u | 0x80000000u);
}
__device__ __forceinline__ float dec_f(unsigned int u) {
    return (u & 0x80000000u) ? __uint_as_float(u ^ 0x80000000u)
                             : __uint_as_float(~u);
}
__device__ __forceinline__ float row_margin(float ax, float xx, float wmaxv) {
    return 0.033f * ax * wmaxv + xx * 1.9073486e-6f + 2e-4f;
}

__device__ __forceinline__ void mma16816(float* c, const uint32_t* a,
                                         const uint32_t* b) {
    asm volatile(
        "mma.sync.aligned.m16n8k16.row.col.f32.bf16.bf16.f32 "
        "{%0,%1,%2,%3}, {%4,%5,%6,%7}, {%8,%9}, {%0,%1,%2,%3};"
        : "+f"(c[0]), "+f"(c[1]), "+f"(c[2]), "+f"(c[3])
        : "r"(a[0]), "r"(a[1]), "r"(a[2]), "r"(a[3]), "r"(b[0]), "r"(b[1]));
}
__device__ __forceinline__ void ldsm4(uint32_t* r, uint32_t addr) {
    asm volatile("ldmatrix.sync.aligned.m8n8.x4.shared.b16 {%0,%1,%2,%3}, [%4];"
                 : "=r"(r[0]), "=r"(r[1]), "=r"(r[2]), "=r"(r[3]) : "r"(addr));
}
__device__ __forceinline__ uint32_t smem_u32(const void* p) {
    uint32_t a;
    asm("{ .reg .u64 t; cvta.to.shared.u64 t, %1; cvt.u32.u64 %0, t; }"
        : "=r"(a) : "l"(p));
    return a;
}

// ---------------------------------------------------------------------------
// Kernel P: exact row stats + bf16 casts + wmax + per-row state init.
// ---------------------------------------------------------------------------
__global__ void prep_kernel(const float* __restrict__ x,
                            const float* __restrict__ w) {
    int t = blockIdx.x * blockDim.x + threadIdx.x;
    if (t < N_ROWS) {
        const float4* p = (const float4*)(x + (size_t)t * DIM);
        uint4* dst = (uint4*)(g_xbf + (size_t)t * DIM);
        float acc = 0.0f, aacc = 0.0f;
#pragma unroll 4
        for (int j = 0; j < 32; j++) {
            float4 v0 = p[2 * j], v1 = p[2 * j + 1];
            acc = __fadd_rn(acc, __fmul_rn(v0.x, v0.x));
            acc = __fadd_rn(acc, __fmul_rn(v0.y, v0.y));
            acc = __fadd_rn(acc, __fmul_rn(v0.z, v0.z));
            acc = __fadd_rn(acc, __fmul_rn(v0.w, v0.w));
            acc = __fadd_rn(acc, __fmul_rn(v1.x, v1.x));
            acc = __fadd_rn(acc, __fmul_rn(v1.y, v1.y));
            acc = __fadd_rn(acc, __fmul_rn(v1.z, v1.z));
            acc = __fadd_rn(acc, __fmul_rn(v1.w, v1.w));
            aacc += fabsf(v0.x) + fabsf(v0.y) + fabsf(v0.z) + fabsf(v0.w)
                  + fabsf(v1.x) + fabsf(v1.y) + fabsf(v1.z) + fabsf(v1.w);
            __nv_bfloat162 b0, b1, b2, b3;
            b0.x = __float2bfloat16_rn(v0.x); b0.y = __float2bfloat16_rn(v0.y);
            b1.x = __float2bfloat16_rn(v0.z); b1.y = __float2bfloat16_rn(v0.w);
            b2.x = __float2bfloat16_rn(v1.x); b2.y = __float2bfloat16_rn(v1.y);
            b3.x = __float2bfloat16_rn(v1.z); b3.y = __float2bfloat16_rn(v1.w);
            uint4 o;
            o.x = *(unsigned int*)&b0; o.y = *(unsigned int*)&b1;
            o.z = *(unsigned int*)&b2; o.w = *(unsigned int*)&b3;
            dst[j] = o;
        }
        g_xx[t] = acc;
        g_ax[t] = aacc;
        g_rowmin[t] = 0xFFFFFFFFu;
        g_cnt[t] = 0u;
    } else if (t < N_ROWS + N_CODES) {
        int r = t - N_ROWS;
        const float4* p = (const float4*)(w + (size_t)r * DIM);
        uint4* dst = (uint4*)(g_wbf + (size_t)r * DIM);
        float acc = 0.0f, amax = 0.0f;
#pragma unroll 4
        for (int j = 0; j < 32; j++) {
            float4 v0 = p[2 * j], v1 = p[2 * j + 1];
            acc = __fadd_rn(acc, __fmul_rn(v0.x, v0.x));
            acc = __fadd_rn(acc, __fmul_rn(v0.y, v0.y));
            acc = __fadd_rn(acc, __fmul_rn(v0.z, v0.z));
            acc = __fadd_rn(acc, __fmul_rn(v0.w, v0.w));
            acc = __fadd_rn(acc, __fmul_rn(v1.x, v1.x));
            acc = __fadd_rn(acc, __fmul_rn(v1.y, v1.y));
            acc = __fadd_rn(acc, __fmul_rn(v1.z, v1.z));
            acc = __fadd_rn(acc, __fmul_rn(v1.w, v1.w));
            amax = fmaxf(amax, fmaxf(fmaxf(fabsf(v0.x), fabsf(v0.y)),
                                     fmaxf(fabsf(v0.z), fabsf(v0.w))));
            amax = fmaxf(amax, fmaxf(fmaxf(fabsf(v1.x), fabsf(v1.y)),
                                     fmaxf(fabsf(v1.z), fabsf(v1.w))));
            __nv_bfloat162 b0, b1, b2, b3;
            b0.x = __float2bfloat16_rn(v0.x); b0.y = __float2bfloat16_rn(v0.y);
            b1.x = __float2bfloat16_rn(v0.z); b1.y = __float2bfloat16_rn(v0.w);
            b2.x = __float2bfloat16_rn(v1.x); b2.y = __float2bfloat16_rn(v1.y);
            b3.x = __float2bfloat16_rn(v1.z); b3.y = __float2bfloat16_rn(v1.w);
            uint4 o;
            o.x = *(unsigned int*)&b0; o.y = *(unsigned int*)&b1;
            o.z = *(unsigned int*)&b2; o.w = *(unsigned int*)&b3;
            dst[j] = o;
        }
        g_ww[r] = acc;
        atomicMax(&g_wmax, __float_as_uint(amax));
    }
}

// ---------------------------------------------------------------------------
// Kernel G: bf16 HMMA GEMM 128x256x256/CTA, 512 threads (16 warps, 4x4),
// warp tile 32x64, ldmatrix fragment loads. Epilogue: per-CTA row-min reduce,
// publish to g_rowmin, push candidates within (rowmin + margin).
// ---------------------------------------------------------------------------
__global__ void __launch_bounds__(512)
vq_gemm_kernel() {
    extern __shared__ char sm[];
    char*  As = sm;                            // [128][528B]
    char*  Bs = sm + AS_BYTES;                 // [256][528B]
    float* ws = (float*)(sm + AS_BYTES + BS_BYTES);
    unsigned int* rmins = (unsigned int*)(sm + AS_BYTES + BS_BYTES + 256 * 4);

    const int tid  = threadIdx.x;
    const int wid  = tid >> 5;
    const int lane = tid & 31;
    const int wm   = wid & 3;      // 0..3, 32 rows each
    const int wn   = wid >> 2;     // 0..3, 64 cols each
    const int g    = lane >> 2;    // 0..7
    const int tg   = lane & 3;     // 0..3
    const int codeBase = blockIdx.x * TN;
    const int rowBase  = blockIdx.y * TM;

    const uint32_t As_u = smem_u32(As);
    const uint32_t Bs_u = smem_u32(Bs);

    // stage A: 4096 16B chunks / 512 threads = 8
#pragma unroll
    for (int i = 0; i < 8; i++) {
        int c = tid + i * 512;
        int r = c >> 5;
        int k16 = c & 31;
        uint4 v = *(const uint4*)(g_xbf + (size_t)(rowBase + r) * DIM + k16 * 8);
        *(uint4*)(As + r * LDAB + k16 * 16) = v;
    }
    // stage B: 8192 chunks / 512 = 16
#pragma unroll
    for (int i = 0; i < 16; i++) {
        int c = tid + i * 512;
        int r = c >> 5;
        int k16 = c & 31;
        uint4 v = *(const uint4*)(g_wbf + (size_t)(codeBase + r) * DIM + k16 * 8);
        *(uint4*)(Bs + r * LDAB + k16 * 16) = v;
    }
    if (tid < 256) ws[tid] = g_ww[codeBase + tid];
    if (tid < 128) rmins[tid] = 0xFFFFFFFFu;
    __syncthreads();

    float acc[2][8][4];
#pragma unroll
    for (int mi = 0; mi < 2; mi++)
#pragma unroll
        for (int ni = 0; ni < 8; ni++)
#pragma unroll
            for (int e = 0; e < 4; e++) acc[mi][ni][e] = 0.0f;

    // ldmatrix lane addressing (same pattern for A and B: k-contiguous rows)
    const int lrow  = (lane & 7) + ((lane >> 3) & 1) * 8;   // row within 16
    const int lkoff = ((lane >> 4) & 1) * 16;               // 0 or 16 bytes

#pragma unroll
    for (int ks = 0; ks < 16; ks++) {
        uint32_t a[2][4];
#pragma unroll
        for (int mi = 0; mi < 2; mi++) {
            uint32_t addr = As_u + (wm * 32 + mi * 16 + lrow) * LDAB
                          + ks * 32 + lkoff;
            ldsm4(a[mi], addr);
        }
        uint32_t b[8][2];
#pragma unroll
        for (int np = 0; np < 4; np++) {
            uint32_t r[4];
            uint32_t addr = Bs_u + (wn * 64 + np * 16 + lrow) * LDAB
                          + ks * 32 + lkoff;
            ldsm4(r, addr);
            b[2 * np][0]     = r[0]; b[2 * np][1]     = r[2];
            b[2 * np + 1][0] = r[1]; b[2 * np + 1][1] = r[3];
        }
#pragma unroll
        for (int mi = 0; mi < 2; mi++)
#pragma unroll
            for (int ni = 0; ni < 8; ni++)
                mma16816(acc[mi][ni], a[mi], b[ni]);
    }

    // distances in place: d = ww[col] - 2*s ; warp-level row mins
    float rmin[2][2];   // [mi][hi]
#pragma unroll
    for (int mi = 0; mi < 2; mi++) {
        float mlo = CUDART_INF_F, mhi = CUDART_INF_F;
#pragma unroll
        for (int ni = 0; ni < 8; ni++) {
            int cloc = wn * 64 + ni * 8 + tg * 2;
            float ww0 = ws[cloc], ww1 = ws[cloc + 1];
            acc[mi][ni][0] = __fmaf_rn(-2.0f, acc[mi][ni][0], ww0);
            acc[mi][ni][1] = __fmaf_rn(-2.0f, acc[mi][ni][1], ww1);
            acc[mi][ni][2] = __fmaf_rn(-2.0f, acc[mi][ni][2], ww0);
            acc[mi][ni][3] = __fmaf_rn(-2.0f, acc[mi][ni][3], ww1);
            mlo = fminf(mlo, fminf(acc[mi][ni][0], acc[mi][ni][1]));
            mhi = fminf(mhi, fminf(acc[mi][ni][2], acc[mi][ni][3]));
        }
        mlo = fminf(mlo, __shfl_xor_sync(0xFFFFFFFF, mlo, 1));
        mlo = fminf(mlo, __shfl_xor_sync(0xFFFFFFFF, mlo, 2));
        mhi = fminf(mhi, __shfl_xor_sync(0xFFFFFFFF, mhi, 1));
        mhi = fminf(mhi, __shfl_xor_sync(0xFFFFFFFF, mhi, 2));
        rmin[mi][0] = mlo; rmin[mi][1] = mhi;
        if (tg == 0) {
            atomicMin(&rmins[wm * 32 + mi * 16 + g], enc_f(mlo));
            atomicMin(&rmins[wm * 32 + mi * 16 + g + 8], enc_f(mhi));
        }
    }
    __syncthreads();
    if (tid < 128) atomicMin(&g_rowmin[rowBase + tid], rmins[tid]);
    __syncthreads();   // ensure our CTA's mins are globally published

    const float wmaxv = __uint_as_float(g_wmax);
#pragma unroll
    for (int mi = 0; mi < 2; mi++) {
#pragma unroll
        for (int h = 0; h < 2; h++) {
            int rl = wm * 32 + mi * 16 + g + h * 8;
            int row = rowBase + rl;
            unsigned int me = g_rowmin[row];   // racy but >= final min
            float thr = dec_f(me) + row_margin(g_ax[row], g_xx[row], wmaxv);
#pragma unroll
            for (int ni = 0; ni < 8; ni++) {
#pragma unroll
                for (int q = 0; q < 2; q++) {
                    float d = acc[mi][ni][h * 2 + q];
                    if (d <= thr) {
                        int code = codeBase + wn * 64 + ni * 8 + tg * 2 + q;
                        unsigned int slot = atomicAdd(&g_cnt[row], 1u);
                        if (slot < CAP)
                            g_cand[(size_t)row * CAP + slot] =
                                make_uint2(enc_f(d), (unsigned int)code);
                    }
                }
            }
        }
    }
}

// ---------------------------------------------------------------------------
// Kernel F: per-row candidate rescore (exact fp32, first-index ties).
// One warp per row. Overflowed rows (cnt > CAP) get a full exact rescan.
// ---------------------------------------------------------------------------
__global__ void __launch_bounds__(256)
select_kernel(const float* __restrict__ x, const float* __restrict__ w) {
    const int row  = blockIdx.x * 8 + (threadIdx.x >> 5);
    const int lane = threadIdx.x & 31;

    const float wmaxv = __uint_as_float(g_wmax);
    const float xx = g_xx[row];
    const float thr = dec_f(g_rowmin[row])
                    + row_margin(g_ax[row], xx, wmaxv);
    const unsigned int cnt = g_cnt[row];
    const float* xr = x + (size_t)row * DIM;

    float bv = CUDART_INF_F;
    int   bi = 0x7fffffff;

    if (cnt <= CAP) {
        const uint2* cl = g_cand + (size_t)row * CAP;
        for (unsigned int s = lane; s < cnt; s += 32) {
            uint2 c = cl[s];
            if (dec_f(c.x) <= thr) {
                int code = (int)c.y;
                const float* wr = w + (size_t)code * DIM;
                float sdot = 0.0f;
#pragma unroll 8
                for (int k = 0; k < DIM; k++)
                    sdot = __fmaf_rn(xr[k], wr[k], sdot);
                float tq = __fadd_rn(xx, g_ww[code]);
                float dq = __fadd_rn(tq, __fmul_rn(-2.0f, sdot));
                if (dq < bv || (dq == bv && code < bi)) { bv = dq; bi = code; }
            }
        }
    } else {
        // overflow fallback (never expected): exact full scan
        for (int code = lane; code < N_CODES; code += 32) {
            const float* wr = w + (size_t)code * DIM;
            float sdot = 0.0f;
#pragma unroll 8
            for (int k = 0; k < DIM; k++)
                sdot = __fmaf_rn(xr[k], wr[k], sdot);
            float tq = __fadd_rn(xx, g_ww[code]);
            float dq = __fadd_rn(tq, __fmul_rn(-2.0f, sdot));
            if (dq < bv || (dq == bv && code < bi)) { bv = dq; bi = code; }
        }
    }
#pragma unroll
    for (int off = 16; off > 0; off >>= 1) {
        float ov = __shfl_xor_sync(0xFFFFFFFF, bv, off);
        int   oi = __shfl_xor_sync(0xFFFFFFFF, bi, off);
        if (ov < bv || (ov == bv && oi < bi)) { bv = ov; bi = oi; }
    }
    if (lane == 0) g_idx[row] = bi;
}

// ---------------------------------------------------------------------------
__global__ void gather_kernel(const float* __restrict__ w, float* __restrict__ out,
                              int out_size) {
    int i = blockIdx.x * blockDim.x + threadIdx.x;
    if (i < N_ROWS * (DIM / 4)) {
        int row = i >> 6;
        int c = i & 63;
        int k = g_idx[row];
        float4 v = ((const float4*)(w + (size_t)k * DIM))[c];
        ((float4*)out)[i] = v;
    }
    if (i < N_ROWS && out_size >= N_ROWS * DIM + N_ROWS) {
        out[N_ROWS * DIM + i] = (float)g_idx[i];
    }
}

// ---------------------------------------------------------------------------
extern "C" void kernel_launch(void* const* d_in, const int* in_sizes, int n_in,
                              void* d_out, int out_size) {
    const float* x = (const float*)d_in[0];
    const float* w = (const float*)d_in[1];
    float* out = (float*)d_out;

    static bool attr_set = false;
    if (!attr_set) {
        cudaFuncSetAttribute(vq_gemm_kernel,
                             cudaFuncAttributeMaxDynamicSharedMemorySize, G_SMEM);
        attr_set = true;
    }

    {
        int total = N_ROWS + N_CODES;
        prep_kernel<<<(total + 255) / 256, 256>>>(x, w);
    }
    {
        dim3 grid(N_CODES / TN, N_ROWS / TM);   // (32, 128)
        vq_gemm_kernel<<<grid, 512, G_SMEM>>>();
    }
    {
        select_kernel<<<N_ROWS / 8, 256>>>(x, w);
    }
    {
        int total4 = N_ROWS * (DIM / 4);
        gather_kernel<<<(total4 + 255) / 256, 256>>>(w, out, out_size);
    }
}

// round 5
// speedup vs baseline: 5.1724x; 1.0149x over previous
#include <cuda_runtime.h>
#include <cuda_bf16.h>
#include <cuda_fp16.h>
#include <math_constants.h>
#include <cstdint>

#define N_ROWS   16384
#define N_CODES  8192
#define DIM      256

#define TM   128         // rows per CTA (persistent)
#define TNI  128         // codes per iteration
#define ITERS (N_CODES / TNI)   // 64
#define LDAB  528        // padded smem row: 264 bf16 = 528 B
#define CAP   1024

#define AS_BYTES (128 * LDAB)      // 67584
#define BS_BYTES (128 * LDAB)      // 67584 per buffer
#define OFF_B0   AS_BYTES
#define OFF_B1   (AS_BYTES + BS_BYTES)
#define OFF_RMIN (AS_BYTES + 2 * BS_BYTES)
#define OFF_CNT  (OFF_RMIN + 128 * 4)
#define OFF_MARG (OFF_CNT + 128 * 4)
#define G_SMEM   (OFF_MARG + 128 * 4)

// ---------------------------------------------------------------------------
__device__ float         g_xx[N_ROWS];
__device__ float         g_ax[N_ROWS];
__device__ float         g_ww[N_CODES];
__device__ unsigned int  g_rowmin[N_ROWS];
__device__ unsigned int  g_cnt[N_ROWS];
__device__ uint2         g_cand[(size_t)N_ROWS * CAP];
__device__ int           g_idx[N_ROWS];
__device__ unsigned int  g_wmax;
__device__ __nv_bfloat16 g_xbf[N_ROWS * DIM];
__device__ __nv_bfloat16 g_wbf[N_CODES * DIM];

__device__ __forceinline__ unsigned int enc_f(float f) {
    unsigned int u = __float_as_uint(f);
    return (u & 0x80000000u) ? ~u : (u | 0x80000000u);
}
__device__ __forceinline__ float dec_f(unsigned int u) {
    return (u & 0x80000000u) ? __uint_as_float(u ^ 0x80000000u)
                             : __uint_as_float(~u);
}
__device__ __forceinline__ float row_margin(float ax, float xx, float wmaxv) {
    return 0.033f * ax * wmaxv + xx * 1.9073486e-6f + 2e-4f;
}
__device__ __forceinline__ void mma16816(float* c, const uint32_t* a,
                                         const uint32_t* b) {
    asm volatile(
        "mma.sync.aligned.m16n8k16.row.col.f32.bf16.bf16.f32 "
        "{%0,%1,%2,%3}, {%4,%5,%6,%7}, {%8,%9}, {%0,%1,%2,%3};"
        : "+f"(c[0]), "+f"(c[1]), "+f"(c[2]), "+f"(c[3])
        : "r"(a[0]), "r"(a[1]), "r"(a[2]), "r"(a[3]), "r"(b[0]), "r"(b[1]));
}
__device__ __forceinline__ void ldsm4(uint32_t* r, uint32_t addr) {
    asm volatile("ldmatrix.sync.aligned.m8n8.x4.shared.b16 {%0,%1,%2,%3}, [%4];"
                 : "=r"(r[0]), "=r"(r[1]), "=r"(r[2]), "=r"(r[3]) : "r"(addr));
}
__device__ __forceinline__ uint32_t smem_u32(const void* p) {
    uint32_t a;
    asm("{ .reg .u64 t; cvta.to.shared.u64 t, %1; cvt.u32.u64 %0, t; }"
        : "=r"(a) : "l"(p));
    return a;
}
__device__ __forceinline__ void cp16(uint32_t dst, const void* src) {
    asm volatile("cp.async.cg.shared.global [%0], [%1], 16;"
                 :: "r"(dst), "l"(src) : "memory");
}

// ---------------------------------------------------------------------------
// Kernel P: exact row stats + bf16 casts + wmax.
// ---------------------------------------------------------------------------
__global__ void prep_kernel(const float* __restrict__ x,
                            const float* __restrict__ w) {
    int t = blockIdx.x * blockDim.x + threadIdx.x;
    if (t < N_ROWS) {
        const float4* p = (const float4*)(x + (size_t)t * DIM);
        uint4* dst = (uint4*)(g_xbf + (size_t)t * DIM);
        float acc = 0.0f, aacc = 0.0f;
#pragma unroll 4
        for (int j = 0; j < 32; j++) {
            float4 v0 = p[2 * j], v1 = p[2 * j + 1];
            acc = __fadd_rn(acc, __fmul_rn(v0.x, v0.x));
            acc = __fadd_rn(acc, __fmul_rn(v0.y, v0.y));
            acc = __fadd_rn(acc, __fmul_rn(v0.z, v0.z));
            acc = __fadd_rn(acc, __fmul_rn(v0.w, v0.w));
            acc = __fadd_rn(acc, __fmul_rn(v1.x, v1.x));
            acc = __fadd_rn(acc, __fmul_rn(v1.y, v1.y));
            acc = __fadd_rn(acc, __fmul_rn(v1.z, v1.z));
            acc = __fadd_rn(acc, __fmul_rn(v1.w, v1.w));
            aacc += fabsf(v0.x) + fabsf(v0.y) + fabsf(v0.z) + fabsf(v0.w)
                  + fabsf(v1.x) + fabsf(v1.y) + fabsf(v1.z) + fabsf(v1.w);
            __nv_bfloat162 b0, b1, b2, b3;
            b0.x = __float2bfloat16_rn(v0.x); b0.y = __float2bfloat16_rn(v0.y);
            b1.x = __float2bfloat16_rn(v0.z); b1.y = __float2bfloat16_rn(v0.w);
            b2.x = __float2bfloat16_rn(v1.x); b2.y = __float2bfloat16_rn(v1.y);
            b3.x = __float2bfloat16_rn(v1.z); b3.y = __float2bfloat16_rn(v1.w);
            uint4 o;
            o.x = *(unsigned int*)&b0; o.y = *(unsigned int*)&b1;
            o.z = *(unsigned int*)&b2; o.w = *(unsigned int*)&b3;
            dst[j] = o;
        }
        g_xx[t] = acc;
        g_ax[t] = aacc;
    } else if (t < N_ROWS + N_CODES) {
        int r = t - N_ROWS;
        const float4* p = (const float4*)(w + (size_t)r * DIM);
        uint4* dst = (uint4*)(g_wbf + (size_t)r * DIM);
        float acc = 0.0f, amax = 0.0f;
#pragma unroll 4
        for (int j = 0; j < 32; j++) {
            float4 v0 = p[2 * j], v1 = p[2 * j + 1];
            acc = __fadd_rn(acc, __fmul_rn(v0.x, v0.x));
            acc = __fadd_rn(acc, __fmul_rn(v0.y, v0.y));
            acc = __fadd_rn(acc, __fmul_rn(v0.z, v0.z));
            acc = __fadd_rn(acc, __fmul_rn(v0.w, v0.w));
            acc = __fadd_rn(acc, __fmul_rn(v1.x, v1.x));
            acc = __fadd_rn(acc, __fmul_rn(v1.y, v1.y));
            acc = __fadd_rn(acc, __fmul_rn(v1.z, v1.z));
            acc = __fadd_rn(acc, __fmul_rn(v1.w, v1.w));
            amax = fmaxf(amax, fmaxf(fmaxf(fabsf(v0.x), fabsf(v0.y)),
                                     fmaxf(fabsf(v0.z), fabsf(v0.w))));
            amax = fmaxf(amax, fmaxf(fmaxf(fabsf(v1.x), fabsf(v1.y)),
                                     fmaxf(fabsf(v1.z), fabsf(v1.w))));
            __nv_bfloat162 b0, b1, b2, b3;
            b0.x = __float2bfloat16_rn(v0.x); b0.y = __float2bfloat16_rn(v0.y);
            b1.x = __float2bfloat16_rn(v0.z); b1.y = __float2bfloat16_rn(v0.w);
            b2.x = __float2bfloat16_rn(v1.x); b2.y = __float2bfloat16_rn(v1.y);
            b3.x = __float2bfloat16_rn(v1.z); b3.y = __float2bfloat16_rn(v1.w);
            uint4 o;
            o.x = *(unsigned int*)&b0; o.y = *(unsigned int*)&b1;
            o.z = *(unsigned int*)&b2; o.w = *(unsigned int*)&b3;
            dst[j] = o;
        }
        g_ww[r] = acc;
        atomicMax(&g_wmax, __float_as_uint(amax));
    }
}

// ---------------------------------------------------------------------------
// Kernel G: persistent-A GEMM. grid=128, 512 threads (16 warps).
// A (128x256 bf16) resident; B streamed in 128-code tiles, 2-deep cp.async.
// Warp tile 64x16 (wm=wid&1 -> 64 rows, wn=wid>>1 -> 16 cols).
// Rows exclusively owned: rowmin + candidate counters in smem.
// ---------------------------------------------------------------------------
__global__ void __launch_bounds__(512)
vq_gemm_kernel() {
    extern __shared__ char sm[];
    char* As = sm;
    unsigned int* rmins = (unsigned int*)(sm + OFF_RMIN);
    unsigned int* cnts  = (unsigned int*)(sm + OFF_CNT);
    float*        margs = (float*)(sm + OFF_MARG);

    const int tid  = threadIdx.x;
    const int wid  = tid >> 5;
    const int lane = tid & 31;
    const int wm   = wid & 1;      // 0..1 -> 64 rows
    const int wn   = wid >> 1;     // 0..7 -> 16 cols
    const int g    = lane >> 2;
    const int tg   = lane & 3;
    const int rowBase = blockIdx.x * TM;

    const uint32_t sm_u  = smem_u32(sm);
    const uint32_t As_u  = sm_u;
    const uint32_t Bu[2] = {sm_u + OFF_B0, sm_u + OFF_B1};

    // prologue: prefetch B tile 0
#pragma unroll
    for (int i = 0; i < 8; i++) {
        int c = tid + i * 512;
        int r = c >> 5;
        int k16 = c & 31;
        cp16(Bu[0] + r * LDAB + k16 * 16,
             g_wbf + (size_t)r * DIM + k16 * 8);
    }
    asm volatile("cp.async.commit_group;" ::: "memory");

    // stage A (once)
#pragma unroll
    for (int i = 0; i < 8; i++) {
        int c = tid + i * 512;
        int r = c >> 5;
        int k16 = c & 31;
        uint4 v = *(const uint4*)(g_xbf + (size_t)(rowBase + r) * DIM + k16 * 8);
        *(uint4*)(As + r * LDAB + k16 * 16) = v;
    }
    if (tid < 128) {
        rmins[tid] = 0xFFFFFFFFu;
        cnts[tid]  = 0u;
        int row = rowBase + tid;
        margs[tid] = row_margin(g_ax[row], g_xx[row],
                                __uint_as_float(g_wmax));
    }
    asm volatile("cp.async.wait_group 0;" ::: "memory");
    __syncthreads();

    const int lrow  = (lane & 7) + ((lane >> 3) & 1) * 8;
    const int lkoff = ((lane >> 4) & 1) * 16;

#pragma unroll 1
    for (int it = 0; it < ITERS; it++) {
        const int codeBase = it * TNI;
        const uint32_t Bcur = Bu[it & 1];

        // prefetch next B tile into the other buffer
        if (it + 1 < ITERS) {
            const int nb = (it + 1) * TNI;
#pragma unroll
            for (int i = 0; i < 8; i++) {
                int c = tid + i * 512;
                int r = c >> 5;
                int k16 = c & 31;
                cp16(Bu[(it + 1) & 1] + r * LDAB + k16 * 16,
                     g_wbf + (size_t)(nb + r) * DIM + k16 * 8);
            }
        }
        asm volatile("cp.async.commit_group;" ::: "memory");

        float acc[4][2][4];
#pragma unroll
        for (int mi = 0; mi < 4; mi++)
#pragma unroll
            for (int ni = 0; ni < 2; ni++)
#pragma unroll
                for (int e = 0; e < 4; e++) acc[mi][ni][e] = 0.0f;

#pragma unroll
        for (int ks = 0; ks < 16; ks++) {
            uint32_t a[4][4];
#pragma unroll
            for (int mi = 0; mi < 4; mi++)
                ldsm4(a[mi], As_u + (wm * 64 + mi * 16 + lrow) * LDAB
                             + ks * 32 + lkoff);
            uint32_t r[4];
            ldsm4(r, Bcur + (wn * 16 + lrow) * LDAB + ks * 32 + lkoff);
            uint32_t b[2][2];
            b[0][0] = r[0]; b[0][1] = r[2];
            b[1][0] = r[1]; b[1][1] = r[3];
#pragma unroll
            for (int mi = 0; mi < 4; mi++)
#pragma unroll
                for (int ni = 0; ni < 2; ni++)
                    mma16816(acc[mi][ni], a[mi], b[ni]);
        }

        // distances + running smem rowmin
        const int c0 = codeBase + wn * 16 + tg * 2;
        float ww0a = __ldg(&g_ww[c0]),      ww1a = __ldg(&g_ww[c0 + 1]);
        float ww0b = __ldg(&g_ww[c0 + 8]),  ww1b = __ldg(&g_ww[c0 + 9]);
#pragma unroll
        for (int mi = 0; mi < 4; mi++) {
            acc[mi][0][0] = __fmaf_rn(-2.0f, acc[mi][0][0], ww0a);
            acc[mi][0][1] = __fmaf_rn(-2.0f, acc[mi][0][1], ww1a);
            acc[mi][0][2] = __fmaf_rn(-2.0f, acc[mi][0][2], ww0a);
            acc[mi][0][3] = __fmaf_rn(-2.0f, acc[mi][0][3], ww1a);
            acc[mi][1][0] = __fmaf_rn(-2.0f, acc[mi][1][0], ww0b);
            acc[mi][1][1] = __fmaf_rn(-2.0f, acc[mi][1][1], ww1b);
            acc[mi][1][2] = __fmaf_rn(-2.0f, acc[mi][1][2], ww0b);
            acc[mi][1][3] = __fmaf_rn(-2.0f, acc[mi][1][3], ww1b);
            float mlo = fminf(fminf(acc[mi][0][0], acc[mi][0][1]),
                              fminf(acc[mi][1][0], acc[mi][1][1]));
            float mhi = fminf(fminf(acc[mi][0][2], acc[mi][0][3]),
                              fminf(acc[mi][1][2], acc[mi][1][3]));
            mlo = fminf(mlo, __shfl_xor_sync(0xFFFFFFFF, mlo, 1));
            mlo = fminf(mlo, __shfl_xor_sync(0xFFFFFFFF, mlo, 2));
            mhi = fminf(mhi, __shfl_xor_sync(0xFFFFFFFF, mhi, 1));
            mhi = fminf(mhi, __shfl_xor_sync(0xFFFFFFFF, mhi, 2));
            if (tg == 0) {
                atomicMin(&rmins[wm * 64 + mi * 16 + g], enc_f(mlo));
                atomicMin(&rmins[wm * 64 + mi * 16 + g + 8], enc_f(mhi));
            }
        }

        asm volatile("cp.async.wait_group 0;" ::: "memory");
        __syncthreads();

        // push candidates within running-min + margin (superset of final set)
#pragma unroll
        for (int mi = 0; mi < 4; mi++) {
#pragma unroll
            for (int h = 0; h < 2; h++) {
                int rl = wm * 64 + mi * 16 + g + h * 8;
                float thr = dec_f(rmins[rl]) + margs[rl];
#pragma unroll
                for (int ni = 0; ni < 2; ni++) {
#pragma unroll
                    for (int q = 0; q < 2; q++) {
                        float d = acc[mi][ni][h * 2 + q];
                        if (d <= thr) {
                            int code = c0 + ni * 8 + q;
                            unsigned int slot = atomicAdd(&cnts[rl], 1u);
                            if (slot < CAP)
                                g_cand[(size_t)(rowBase + rl) * CAP + slot] =
                                    make_uint2(enc_f(d), (unsigned int)code);
                        }
                    }
                }
            }
        }
    }

    __syncthreads();
    if (tid < 128) {
        g_rowmin[rowBase + tid] = rmins[tid];   // exact final approx-min
        g_cnt[rowBase + tid]    = cnts[tid];
    }
}

// ---------------------------------------------------------------------------
// Kernel F: per-row candidate rescore (exact fp32, first-index ties).
// ---------------------------------------------------------------------------
__global__ void __launch_bounds__(256)
select_kernel(const float* __restrict__ x, const float* __restrict__ w) {
    const int row  = blockIdx.x * 8 + (threadIdx.x >> 5);
    const int lane = threadIdx.x & 31;

    const float wmaxv = __uint_as_float(g_wmax);
    const float xx = g_xx[row];
    const float thr = dec_f(g_rowmin[row]) + row_margin(g_ax[row], xx, wmaxv);
    const unsigned int cnt = g_cnt[row];
    const float* xr = x + (size_t)row * DIM;

    float bv = CUDART_INF_F;
    int   bi = 0x7fffffff;

    if (cnt <= CAP) {
        const uint2* cl = g_cand + (size_t)row * CAP;
        for (unsigned int s = lane; s < cnt; s += 32) {
            uint2 c = cl[s];
            if (dec_f(c.x) <= thr) {
                int code = (int)c.y;
                const float* wr = w + (size_t)code * DIM;
                float sdot = 0.0f;
#pragma unroll 8
                for (int k = 0; k < DIM; k++)
                    sdot = __fmaf_rn(xr[k], wr[k], sdot);
                float tq = __fadd_rn(xx, g_ww[code]);
                float dq = __fadd_rn(tq, __fmul_rn(-2.0f, sdot));
                if (dq < bv || (dq == bv && code < bi)) { bv = dq; bi = code; }
            }
        }
    } else {
        for (int code = lane; code < N_CODES; code += 32) {
            const float* wr = w + (size_t)code * DIM;
            float sdot = 0.0f;
#pragma unroll 8
            for (int k = 0; k < DIM; k++)
                sdot = __fmaf_rn(xr[k], wr[k], sdot);
            float tq = __fadd_rn(xx, g_ww[code]);
            float dq = __fadd_rn(tq, __fmul_rn(-2.0f, sdot));
            if (dq < bv || (dq == bv && code < bi)) { bv = dq; bi = code; }
        }
    }
#pragma unroll
    for (int off = 16; off > 0; off >>= 1) {
        float ov = __shfl_xor_sync(0xFFFFFFFF, bv, off);
        int   oi = __shfl_xor_sync(0xFFFFFFFF, bi, off);
        if (ov < bv || (ov == bv && oi < bi)) { bv = ov; bi = oi; }
    }
    if (lane == 0) g_idx[row] = bi;
}

// ---------------------------------------------------------------------------
__global__ void gather_kernel(const float* __restrict__ w, float* __restrict__ out,
                              int out_size) {
    int i = blockIdx.x * blockDim.x + threadIdx.x;
    if (i < N_ROWS * (DIM / 4)) {
        int row = i >> 6;
        int c = i & 63;
        int k = g_idx[row];
        float4 v = ((const float4*)(w + (size_t)k * DIM))[c];
        ((float4*)out)[i] = v;
    }
    if (i < N_ROWS && out_size >= N_ROWS * DIM + N_ROWS) {
        out[N_ROWS * DIM + i] = (float)g_idx[i];
    }
}

// ---------------------------------------------------------------------------
extern "C" void kernel_launch(void* const* d_in, const int* in_sizes, int n_in,
                              void* d_out, int out_size) {
    const float* x = (const float*)d_in[0];
    const float* w = (const float*)d_in[1];
    float* out = (float*)d_out;

    static bool attr_set = false;
    if (!attr_set) {
        cudaFuncSetAttribute(vq_gemm_kernel,
                             cudaFuncAttributeMaxDynamicSharedMemorySize, G_SMEM);
        attr_set = true;
    }

    {
        int total = N_ROWS + N_CODES;
        prep_kernel<<<(total + 255) / 256, 256>>>(x, w);
    }
    {
        vq_gemm_kernel<<<N_ROWS / TM, 512, G_SMEM>>>();   // 128 CTAs
    }
    {
        select_kernel<<<N_ROWS / 8, 256>>>(x, w);
    }
    {
        int total4 = N_ROWS * (DIM / 4);
        gather_kernel<<<(total4 + 255) / 256, 256>>>(w, out, out_size);
    }
}

// round 6
// speedup vs baseline: 5.2878x; 1.0223x over previous
#include <cuda_runtime.h>
#include <cuda_bf16.h>
#include <cuda_fp16.h>
#include <math_constants.h>
#include <cstdint>

#define N_ROWS   16384
#define N_CODES  8192
#define DIM      256

#define TM   128         // rows per CTA (persistent)
#define TNI  128         // codes per iteration
#define ITERS (N_CODES / TNI)   // 64
#define LDAB  528        // padded smem row: 264 bf16 = 528 B
#define CAP   1024

#define AS_BYTES (128 * LDAB)      // 67584
#define BS_BYTES (128 * LDAB)      // 67584 per buffer
#define OFF_B0   AS_BYTES
#define OFF_B1   (AS_BYTES + BS_BYTES)
#define OFF_RMIN (AS_BYTES + 2 * BS_BYTES)
#define OFF_CNT  (OFF_RMIN + 128 * 4)
#define OFF_MARG (OFF_CNT + 128 * 4)
#define G_SMEM   (OFF_MARG + 128 * 4)

// ---------------------------------------------------------------------------
__device__ float         g_xx[N_ROWS];
__device__ float         g_ax[N_ROWS];
__device__ float         g_ww[N_CODES];
__device__ unsigned int  g_rowmin[N_ROWS];
__device__ unsigned int  g_cnt[N_ROWS];
__device__ uint2         g_cand[(size_t)N_ROWS * CAP];
__device__ int           g_idx[N_ROWS];
__device__ unsigned int  g_wmax;
__device__ __nv_bfloat16 g_xbf[N_ROWS * DIM];
__device__ __nv_bfloat16 g_wbf[N_CODES * DIM];

__device__ __forceinline__ unsigned int enc_f(float f) {
    unsigned int u = __float_as_uint(f);
    return (u & 0x80000000u) ? ~u : (u | 0x80000000u);
}
__device__ __forceinline__ float dec_f(unsigned int u) {
    return (u & 0x80000000u) ? __uint_as_float(u ^ 0x80000000u)
                             : __uint_as_float(~u);
}
__device__ __forceinline__ float row_margin(float ax, float xx, float wmaxv) {
    return 0.033f * ax * wmaxv + xx * 1.9073486e-6f + 2e-4f;
}
__device__ __forceinline__ void mma16816(float* c, const uint32_t* a,
                                         const uint32_t* b) {
    asm volatile(
        "mma.sync.aligned.m16n8k16.row.col.f32.bf16.bf16.f32 "
        "{%0,%1,%2,%3}, {%4,%5,%6,%7}, {%8,%9}, {%0,%1,%2,%3};"
        : "+f"(c[0]), "+f"(c[1]), "+f"(c[2]), "+f"(c[3])
        : "r"(a[0]), "r"(a[1]), "r"(a[2]), "r"(a[3]), "r"(b[0]), "r"(b[1]));
}
__device__ __forceinline__ void ldsm4(uint32_t* r, uint32_t addr) {
    asm volatile("ldmatrix.sync.aligned.m8n8.x4.shared.b16 {%0,%1,%2,%3}, [%4];"
                 : "=r"(r[0]), "=r"(r[1]), "=r"(r[2]), "=r"(r[3]) : "r"(addr));
}
__device__ __forceinline__ uint32_t smem_u32(const void* p) {
    uint32_t a;
    asm("{ .reg .u64 t; cvta.to.shared.u64 t, %1; cvt.u32.u64 %0, t; }"
        : "=r"(a) : "l"(p));
    return a;
}
__device__ __forceinline__ void cp16(uint32_t dst, const void* src) {
    asm volatile("cp.async.cg.shared.global [%0], [%1], 16;"
                 :: "r"(dst), "l"(src) : "memory");
}

// ---------------------------------------------------------------------------
// Kernel P: exact row stats + bf16 casts + wmax.
// ---------------------------------------------------------------------------
__global__ void prep_kernel(const float* __restrict__ x,
                            const float* __restrict__ w) {
    int t = blockIdx.x * blockDim.x + threadIdx.x;
    if (t < N_ROWS) {
        const float4* p = (const float4*)(x + (size_t)t * DIM);
        uint4* dst = (uint4*)(g_xbf + (size_t)t * DIM);
        float acc = 0.0f, aacc = 0.0f;
#pragma unroll 4
        for (int j = 0; j < 32; j++) {
            float4 v0 = p[2 * j], v1 = p[2 * j + 1];
            acc = __fadd_rn(acc, __fmul_rn(v0.x, v0.x));
            acc = __fadd_rn(acc, __fmul_rn(v0.y, v0.y));
            acc = __fadd_rn(acc, __fmul_rn(v0.z, v0.z));
            acc = __fadd_rn(acc, __fmul_rn(v0.w, v0.w));
            acc = __fadd_rn(acc, __fmul_rn(v1.x, v1.x));
            acc = __fadd_rn(acc, __fmul_rn(v1.y, v1.y));
            acc = __fadd_rn(acc, __fmul_rn(v1.z, v1.z));
            acc = __fadd_rn(acc, __fmul_rn(v1.w, v1.w));
            aacc += fabsf(v0.x) + fabsf(v0.y) + fabsf(v0.z) + fabsf(v0.w)
                  + fabsf(v1.x) + fabsf(v1.y) + fabsf(v1.z) + fabsf(v1.w);
            __nv_bfloat162 b0, b1, b2, b3;
            b0.x = __float2bfloat16_rn(v0.x); b0.y = __float2bfloat16_rn(v0.y);
            b1.x = __float2bfloat16_rn(v0.z); b1.y = __float2bfloat16_rn(v0.w);
            b2.x = __float2bfloat16_rn(v1.x); b2.y = __float2bfloat16_rn(v1.y);
            b3.x = __float2bfloat16_rn(v1.z); b3.y = __float2bfloat16_rn(v1.w);
            uint4 o;
            o.x = *(unsigned int*)&b0; o.y = *(unsigned int*)&b1;
            o.z = *(unsigned int*)&b2; o.w = *(unsigned int*)&b3;
            dst[j] = o;
        }
        g_xx[t] = acc;
        g_ax[t] = aacc;
    } else if (t < N_ROWS + N_CODES) {
        int r = t - N_ROWS;
        const float4* p = (const float4*)(w + (size_t)r * DIM);
        uint4* dst = (uint4*)(g_wbf + (size_t)r * DIM);
        float acc = 0.0f, amax = 0.0f;
#pragma unroll 4
        for (int j = 0; j < 32; j++) {
            float4 v0 = p[2 * j], v1 = p[2 * j + 1];
            acc = __fadd_rn(acc, __fmul_rn(v0.x, v0.x));
            acc = __fadd_rn(acc, __fmul_rn(v0.y, v0.y));
            acc = __fadd_rn(acc, __fmul_rn(v0.z, v0.z));
            acc = __fadd_rn(acc, __fmul_rn(v0.w, v0.w));
            acc = __fadd_rn(acc, __fmul_rn(v1.x, v1.x));
            acc = __fadd_rn(acc, __fmul_rn(v1.y, v1.y));
            acc = __fadd_rn(acc, __fmul_rn(v1.z, v1.z));
            acc = __fadd_rn(acc, __fmul_rn(v1.w, v1.w));
            amax = fmaxf(amax, fmaxf(fmaxf(fabsf(v0.x), fabsf(v0.y)),
                                     fmaxf(fabsf(v0.z), fabsf(v0.w))));
            amax = fmaxf(amax, fmaxf(fmaxf(fabsf(v1.x), fabsf(v1.y)),
                                     fmaxf(fabsf(v1.z), fabsf(v1.w))));
            __nv_bfloat162 b0, b1, b2, b3;
            b0.x = __float2bfloat16_rn(v0.x); b0.y = __float2bfloat16_rn(v0.y);
            b1.x = __float2bfloat16_rn(v0.z); b1.y = __float2bfloat16_rn(v0.w);
            b2.x = __float2bfloat16_rn(v1.x); b2.y = __float2bfloat16_rn(v1.y);
            b3.x = __float2bfloat16_rn(v1.z); b3.y = __float2bfloat16_rn(v1.w);
            uint4 o;
            o.x = *(unsigned int*)&b0; o.y = *(unsigned int*)&b1;
            o.z = *(unsigned int*)&b2; o.w = *(unsigned int*)&b3;
            dst[j] = o;
        }
        g_ww[r] = acc;
        atomicMax(&g_wmax, __float_as_uint(amax));
    }
}

// ---------------------------------------------------------------------------
// Kernel G: persistent-A GEMM. grid=128, 512 threads (16 warps).
// A (128x256 bf16) resident; B streamed in 128-code tiles, 2-deep cp.async.
// Warp tile 64x16 (wm=wid&1 -> 64 rows, wn=wid>>1 -> 16 cols).
// Rows exclusively owned: rowmin + candidate counters in smem.
// ---------------------------------------------------------------------------
__global__ void __launch_bounds__(512)
vq_gemm_kernel() {
    extern __shared__ char sm[];
    char* As = sm;
    unsigned int* rmins = (unsigned int*)(sm + OFF_RMIN);
    unsigned int* cnts  = (unsigned int*)(sm + OFF_CNT);
    float*        margs = (float*)(sm + OFF_MARG);

    const int tid  = threadIdx.x;
    const int wid  = tid >> 5;
    const int lane = tid & 31;
    const int wm   = wid & 1;      // 0..1 -> 64 rows
    const int wn   = wid >> 1;     // 0..7 -> 16 cols
    const int g    = lane >> 2;
    const int tg   = lane & 3;
    const int rowBase = blockIdx.x * TM;

    const uint32_t sm_u  = smem_u32(sm);
    const uint32_t As_u  = sm_u;
    const uint32_t Bu[2] = {sm_u + OFF_B0, sm_u + OFF_B1};

    // prologue: prefetch B tile 0
#pragma unroll
    for (int i = 0; i < 8; i++) {
        int c = tid + i * 512;
        int r = c >> 5;
        int k16 = c & 31;
        cp16(Bu[0] + r * LDAB + k16 * 16,
             g_wbf + (size_t)r * DIM + k16 * 8);
    }
    asm volatile("cp.async.commit_group;" ::: "memory");

    // stage A (once)
#pragma unroll
    for (int i = 0; i < 8; i++) {
        int c = tid + i * 512;
        int r = c >> 5;
        int k16 = c & 31;
        uint4 v = *(const uint4*)(g_xbf + (size_t)(rowBase + r) * DIM + k16 * 8);
        *(uint4*)(As + r * LDAB + k16 * 16) = v;
    }
    if (tid < 128) {
        rmins[tid] = 0xFFFFFFFFu;
        cnts[tid]  = 0u;
        int row = rowBase + tid;
        margs[tid] = row_margin(g_ax[row], g_xx[row],
                                __uint_as_float(g_wmax));
    }
    asm volatile("cp.async.wait_group 0;" ::: "memory");
    __syncthreads();

    const int lrow  = (lane & 7) + ((lane >> 3) & 1) * 8;
    const int lkoff = ((lane >> 4) & 1) * 16;

#pragma unroll 1
    for (int it = 0; it < ITERS; it++) {
        const int codeBase = it * TNI;
        const uint32_t Bcur = Bu[it & 1];

        // prefetch next B tile into the other buffer
        if (it + 1 < ITERS) {
            const int nb = (it + 1) * TNI;
#pragma unroll
            for (int i = 0; i < 8; i++) {
                int c = tid + i * 512;
                int r = c >> 5;
                int k16 = c & 31;
                cp16(Bu[(it + 1) & 1] + r * LDAB + k16 * 16,
                     g_wbf + (size_t)(nb + r) * DIM + k16 * 8);
            }
        }
        asm volatile("cp.async.commit_group;" ::: "memory");

        float acc[4][2][4];
#pragma unroll
        for (int mi = 0; mi < 4; mi++)
#pragma unroll
            for (int ni = 0; ni < 2; ni++)
#pragma unroll
                for (int e = 0; e < 4; e++) acc[mi][ni][e] = 0.0f;

#pragma unroll
        for (int ks = 0; ks < 16; ks++) {
            uint32_t a[4][4];
#pragma unroll
            for (int mi = 0; mi < 4; mi++)
                ldsm4(a[mi], As_u + (wm * 64 + mi * 16 + lrow) * LDAB
                             + ks * 32 + lkoff);
            uint32_t r[4];
            ldsm4(r, Bcur + (wn * 16 + lrow) * LDAB + ks * 32 + lkoff);
            uint32_t b[2][2];
            b[0][0] = r[0]; b[0][1] = r[2];
            b[1][0] = r[1]; b[1][1] = r[3];
#pragma unroll
            for (int mi = 0; mi < 4; mi++)
#pragma unroll
                for (int ni = 0; ni < 2; ni++)
                    mma16816(acc[mi][ni], a[mi], b[ni]);
        }

        // distances + running smem rowmin
        const int c0 = codeBase + wn * 16 + tg * 2;
        float ww0a = __ldg(&g_ww[c0]),      ww1a = __ldg(&g_ww[c0 + 1]);
        float ww0b = __ldg(&g_ww[c0 + 8]),  ww1b = __ldg(&g_ww[c0 + 9]);
#pragma unroll
        for (int mi = 0; mi < 4; mi++) {
            acc[mi][0][0] = __fmaf_rn(-2.0f, acc[mi][0][0], ww0a);
            acc[mi][0][1] = __fmaf_rn(-2.0f, acc[mi][0][1], ww1a);
            acc[mi][0][2] = __fmaf_rn(-2.0f, acc[mi][0][2], ww0a);
            acc[mi][0][3] = __fmaf_rn(-2.0f, acc[mi][0][3], ww1a);
            acc[mi][1][0] = __fmaf_rn(-2.0f, acc[mi][1][0], ww0b);
            acc[mi][1][1] = __fmaf_rn(-2.0f, acc[mi][1][1], ww1b);
            acc[mi][1][2] = __fmaf_rn(-2.0f, acc[mi][1][2], ww0b);
            acc[mi][1][3] = __fmaf_rn(-2.0f, acc[mi][1][3], ww1b);
            float mlo = fminf(fminf(acc[mi][0][0], acc[mi][0][1]),
                              fminf(acc[mi][1][0], acc[mi][1][1]));
            float mhi = fminf(fminf(acc[mi][0][2], acc[mi][0][3]),
                              fminf(acc[mi][1][2], acc[mi][1][3]));
            mlo = fminf(mlo, __shfl_xor_sync(0xFFFFFFFF, mlo, 1));
            mlo = fminf(mlo, __shfl_xor_sync(0xFFFFFFFF, mlo, 2));
            mhi = fminf(mhi, __shfl_xor_sync(0xFFFFFFFF, mhi, 1));
            mhi = fminf(mhi, __shfl_xor_sync(0xFFFFFFFF, mhi, 2));
            if (tg == 0) {
                atomicMin(&rmins[wm * 64 + mi * 16 + g], enc_f(mlo));
                atomicMin(&rmins[wm * 64 + mi * 16 + g + 8], enc_f(mhi));
            }
        }

        asm volatile("cp.async.wait_group 0;" ::: "memory");
        __syncthreads();

        // push candidates within running-min + margin (superset of final set)
#pragma unroll
        for (int mi = 0; mi < 4; mi++) {
#pragma unroll
            for (int h = 0; h < 2; h++) {
                int rl = wm * 64 + mi * 16 + g + h * 8;
                float thr = dec_f(rmins[rl]) + margs[rl];
#pragma unroll
                for (int ni = 0; ni < 2; ni++) {
#pragma unroll
                    for (int q = 0; q < 2; q++) {
                        float d = acc[mi][ni][h * 2 + q];
                        if (d <= thr) {
                            int code = c0 + ni * 8 + q;
                            unsigned int slot = atomicAdd(&cnts[rl], 1u);
                            if (slot < CAP)
                                g_cand[(size_t)(rowBase + rl) * CAP + slot] =
                                    make_uint2(enc_f(d), (unsigned int)code);
                        }
                    }
                }
            }
        }
    }

    __syncthreads();
    if (tid < 128) {
        g_rowmin[rowBase + tid] = rmins[tid];   // exact final approx-min
        g_cnt[rowBase + tid]    = cnts[tid];
    }
}

// ---------------------------------------------------------------------------
// Kernel F: per-row candidate rescore (exact fp32, first-index ties).
// ---------------------------------------------------------------------------
__global__ void __launch_bounds__(256)
select_kernel(const float* __restrict__ x, const float* __restrict__ w) {
    const int row  = blockIdx.x * 8 + (threadIdx.x >> 5);
    const int lane = threadIdx.x & 31;

    const float wmaxv = __uint_as_float(g_wmax);
    const float xx = g_xx[row];
    const float thr = dec_f(g_rowmin[row]) + row_margin(g_ax[row], xx, wmaxv);
    const unsigned int cnt = g_cnt[row];
    const float* xr = x + (size_t)row * DIM;

    float bv = CUDART_INF_F;
    int   bi = 0x7fffffff;

    if (cnt <= CAP) {
        const uint2* cl = g_cand + (size_t)row * CAP;
        for (unsigned int s = lane; s < cnt; s += 32) {
            uint2 c = cl[s];
            if (dec_f(c.x) <= thr) {
                int code = (int)c.y;
                const float* wr = w + (size_t)code * DIM;
                float sdot = 0.0f;
#pragma unroll 8
                for (int k = 0; k < DIM; k++)
                    sdot = __fmaf_rn(xr[k], wr[k], sdot);
                float tq = __fadd_rn(xx, g_ww[code]);
                float dq = __fadd_rn(tq, __fmul_rn(-2.0f, sdot));
                if (dq < bv || (dq == bv && code < bi)) { bv = dq; bi = code; }
            }
        }
    } else {
        for (int code = lane; code < N_CODES; code += 32) {
            const float* wr = w + (size_t)code * DIM;
            float sdot = 0.0f;
#pragma unroll 8
            for (int k = 0; k < DIM; k++)
                sdot = __fmaf_rn(xr[k], wr[k], sdot);
            float tq = __fadd_rn(xx, g_ww[code]);
            float dq = __fadd_rn(tq, __fmul_rn(-2.0f, sdot));
            if (dq < bv || (dq == bv && code < bi)) { bv = dq; bi = code; }
        }
    }
#pragma unroll
    for (int off = 16; off > 0; off >>= 1) {
        float ov = __shfl_xor_sync(0xFFFFFFFF, bv, off);
        int   oi = __shfl_xor_sync(0xFFFFFFFF, bi, off);
        if (ov < bv || (ov == bv && oi < bi)) { bv = ov; bi = oi; }
    }
    if (lane == 0) g_idx[row] = bi;
}

// ---------------------------------------------------------------------------
__global__ void gather_kernel(const float* __restrict__ w, float* __restrict__ out,
                              int out_size) {
    int i = blockIdx.x * blockDim.x + threadIdx.x;
    if (i < N_ROWS * (DIM / 4)) {
        int row = i >> 6;
        int c = i & 63;
        int k = g_idx[row];
        float4 v = ((const float4*)(w + (size_t)k * DIM))[c];
        ((float4*)out)[i] = v;
    }
    if (i < N_ROWS && out_size >= N_ROWS * DIM + N_ROWS) {
        out[N_ROWS * DIM + i] = (float)g_idx[i];
    }
}

// ---------------------------------------------------------------------------
extern "C" void kernel_launch(void* const* d_in, const int* in_sizes, int n_in,
                              void* d_out, int out_size) {
    const float* x = (const float*)d_in[0];
    const float* w = (const float*)d_in[1];
    float* out = (float*)d_out;

    static bool attr_set = false;
    if (!attr_set) {
        cudaFuncSetAttribute(vq_gemm_kernel,
                             cudaFuncAttributeMaxDynamicSharedMemorySize, G_SMEM);
        attr_set = true;
    }

    {
        int total = N_ROWS + N_CODES;
        prep_kernel<<<(total + 255) / 256, 256>>>(x, w);
    }
    {
        vq_gemm_kernel<<<N_ROWS / TM, 512, G_SMEM>>>();   // 128 CTAs
    }
    {
        select_kernel<<<N_ROWS / 8, 256>>>(x, w);
    }
    {
        int total4 = N_ROWS * (DIM / 4);
        gather_kernel<<<(total4 + 255) / 256, 256>>>(w, out, out_size);
    }
}